// round 13
// baseline (speedup 1.0000x reference)
#include <cuda_runtime.h>
#include <stdint.h>

#define DEVINL __device__ __forceinline__

static constexpr int BATCH  = 131072;
static constexpr int KDIM   = 256;
static constexpr int NDIM   = 256;
static constexpr int MTILE  = 64;
static constexpr int NTILES = BATCH / MTILE;   // 2048
static constexpr int THREADS = 256;            // 8 warps: 2x4 warp grid, warp tile 32x64
static constexpr int AFRAG  = MTILE * KDIM / 4;  // 4096 float4-equivalents per A tile

// Padded row stride (bytes) for s8 tiles in SMEM: 272 = 16*17.
// 272/4 = 68 == 4 (mod 32) -> 8 consecutive rows cover all 32 banks exactly
// once for 16B/row accesses: conflict-free ldmatrix and 16B vector copies.
static constexpr int ROWB = 272;
static constexpr int ATILE_B = MTILE * ROWB;    // 17408

static constexpr int SM_W  = 0;                 // W tile: 256 x 272 = 69632
static constexpr int SM_A0 = NDIM * ROWB;       // A ping  buffer
static constexpr int SM_A1 = SM_A0 + ATILE_B;   // A pong  buffer
static constexpr int SMEM_TOTAL = SM_A1 + ATILE_B;  // 104448 B -> 2 CTAs/SM

// per-CTA partial abs-max, fully overwritten by the GEMM kernel every replay
__device__ int g_partial[NTILES];
// raw s32 GEMM accumulators (gemm writes, finalize reads) — 128 MB static scratch
__device__ int g_temp[(size_t)BATCH * NDIM];

DEVINL uint32_t smem_u32(const void* p) {
    uint32_t a;
    asm("{ .reg .u64 t; cvta.to.shared.u64 t, %1; cvt.u32.u64 %0, t; }" : "=r"(a) : "l"(p));
    return a;
}

// ldmatrix x4 (b16 view of s8 data). sm_75+ PTX, no 'a'-target features.
DEVINL void ldsm4(uint32_t* r, uint32_t addr) {
    asm volatile("ldmatrix.sync.aligned.m8n8.x4.shared.b16 {%0,%1,%2,%3}, [%4];"
                 : "=r"(r[0]), "=r"(r[1]), "=r"(r[2]), "=r"(r[3]) : "r"(addr));
}

// s8 x s8 -> s32 mma (sm_80+): D[16x8] += A[16x32](row) * B[32x8](col)
DEVINL void mma_s8(int* c, const uint32_t* a, const uint32_t* b) {
    asm volatile(
        "mma.sync.aligned.m16n8k32.row.col.s32.s8.s8.s32 "
        "{%0,%1,%2,%3}, {%4,%5,%6,%7}, {%8,%9}, {%0,%1,%2,%3};"
        : "+r"(c[0]), "+r"(c[1]), "+r"(c[2]), "+r"(c[3])
        : "r"(a[0]), "r"(a[1]), "r"(a[2]), "r"(a[3]), "r"(b[0]), "r"(b[1]));
}

DEVINL uint32_t pack_s8(float4 f) {
    int b0 = __float2int_rn(f.x) & 255, b1 = __float2int_rn(f.y) & 255;
    int b2 = __float2int_rn(f.z) & 255, b3 = __float2int_rn(f.w) & 255;
    return (uint32_t)(b0 | (b1 << 8) | (b2 << 16) | (b3 << 24));
}

// RoundShift, exact integer replica of the fp reference. pos branch: floor-shift
// + remainder bit (s-1), clip [-127,127]. !pos branch: numpy astype(int8) wrap
// (exact: !pos implies |x| <= 128).
DEVINL float round_shift_f(int x, int shift, bool pos) {
    int v;
    if (pos) {
        v = (x >> shift) + ((x >> (shift - 1)) & 1);
        v = v < -127 ? -127 : (v > 127 ? 127 : v);
    } else {
        v = (int)(signed char)(x & 255);
    }
    return (float)v;
}

// store one packed A word into the padded s8 tile (f in [0, AFRAG))
DEVINL void sts_a(char* smem, int buf_off, int f, uint32_t u) {
    int row = f >> 6, fi = f & 63;
    *reinterpret_cast<uint32_t*>(smem + buf_off + row * ROWB + fi * 4) = u;
}

// ---------------- Phase 0: s8 GEMM -> raw s32 temp + per-CTA abs-max ----------------
__global__ void __launch_bounds__(THREADS, 2)
gemm_kernel(const float* __restrict__ act, const float* __restrict__ weight)
{
    extern __shared__ char smem[];
    __shared__ int red[8];
    const uint32_t sb = smem_u32(smem);
    const int tid = threadIdx.x;
    const int wid = tid >> 5;
    const int lid = tid & 31;
    const int mw = (wid >> 2) * 32;   // warp M base within the 64-row tile
    const int nw = (wid & 3) * 64;    // warp N base within 256 cols

    // stage W [N=256][K=256] fp32 -> s8, padded rows, once per CTA
    {
        const float4* w4 = reinterpret_cast<const float4*>(weight);
        for (int f = tid; f < NDIM * KDIM / 4; f += THREADS) {
            int row = f >> 6, fi = f & 63;              // 64 float4 per K-row
            *reinterpret_cast<uint32_t*>(smem + SM_W + row * ROWB + fi * 4) = pack_s8(w4[f]);
        }
    }

    int lmax = 0;
    const int gsz = (int)gridDim.x;
    const int c = (NTILES - (int)blockIdx.x + gsz - 1) / gsz;

    // prologue: plain-stage tile 0 into buffer 0
    {
        const float4* a4 = reinterpret_cast<const float4*>(act) + (size_t)blockIdx.x * AFRAG;
        #pragma unroll
        for (int i = 0; i < AFRAG / THREADS; i++) {
            int f = tid + i * THREADS;
            sts_a(smem, SM_A0, f, pack_s8(__ldcs(&a4[f])));
        }
    }
    __syncthreads();

    for (int j = 0; j < c; j++) {
        const int tile = (int)blockIdx.x + j * gsz;
        const int cbuf = SM_A0 + (j & 1) * ATILE_B;          // MMA reads this
        const int nbuf = SM_A0 + ((j + 1) & 1) * ATILE_B;    // prefetch writes this
        const bool pf = (j + 1 < c);
        const float4* a4n = reinterpret_cast<const float4*>(act)
                          + (size_t)(tile + gsz) * AFRAG;

        int acc[16][4];
        #pragma unroll
        for (int i = 0; i < 16; i++)
            #pragma unroll
            for (int r = 0; r < 4; r++) acc[i][r] = 0;

        // software pipeline: cur holds data for pack/STS this step; nxt in flight
        float4 cur0, cur1, nxt0, nxt1;
        if (pf) {
            cur0 = __ldcs(&a4n[tid]);
            cur1 = __ldcs(&a4n[tid + THREADS]);
        }

        // K=256 in 8 steps of 32, with next-tile staging interleaved
        #pragma unroll
        for (int ks = 0; ks < 8; ks++) {
            // issue next prefetch loads early (latency hidden by ldsm+mma below)
            if (pf && ks < 7) {
                nxt0 = __ldcs(&a4n[tid + (2 * ks + 2) * THREADS]);
                nxt1 = __ldcs(&a4n[tid + (2 * ks + 3) * THREADS]);
            }

            const int kb = ks * 32;
            uint32_t a[2][4], b[8][2];
            #pragma unroll
            for (int mt = 0; mt < 2; mt++) {
                int row = mw + mt * 16 + ((lid >> 3) & 1) * 8 + (lid & 7);
                uint32_t addr = sb + cbuf + row * ROWB + kb + (((lid >> 4) & 1) << 4);
                ldsm4(a[mt], addr);
            }
            #pragma unroll
            for (int p = 0; p < 4; p++) {
                int nrow = nw + p * 16 + (((lid >> 4) & 1) << 3) + (lid & 7);
                uint32_t addr = sb + SM_W + nrow * ROWB + kb + (((lid >> 3) & 1) << 4);
                uint32_t t4[4];
                ldsm4(t4, addr);
                b[2 * p][0] = t4[0]; b[2 * p][1] = t4[1];
                b[2 * p + 1][0] = t4[2]; b[2 * p + 1][1] = t4[3];
            }
            #pragma unroll
            for (int mt = 0; mt < 2; mt++)
                #pragma unroll
                for (int nt = 0; nt < 8; nt++)
                    mma_s8(acc[mt * 8 + nt], a[mt], b[nt]);

            // pack + STS the pair loaded one step ago (into the inactive buffer)
            if (pf) {
                sts_a(smem, nbuf, tid + (2 * ks) * THREADS,     pack_s8(cur0));
                sts_a(smem, nbuf, tid + (2 * ks + 1) * THREADS, pack_s8(cur1));
                cur0 = nxt0;
                cur1 = nxt1;
            }
        }

        // epilogue: abs-max + raw s32 store (C quads -> 8B-aligned int2 stores)
        const size_t rowbase = (size_t)tile * MTILE;
        #pragma unroll
        for (int mt = 0; mt < 2; mt++)
            #pragma unroll
            for (int nt = 0; nt < 8; nt++) {
                const int* cc = acc[mt * 8 + nt];
                #pragma unroll
                for (int r = 0; r < 4; r++) {
                    int x = cc[r];
                    lmax = max(lmax, max(x, -x));
                }
                int r0  = mw + mt * 16 + (lid >> 2);
                int col = nw + nt * 8 + 2 * (lid & 3);
                __stcs(reinterpret_cast<int2*>(g_temp + ((rowbase + r0) << 8) + col),
                       make_int2(cc[0], cc[1]));
                __stcs(reinterpret_cast<int2*>(g_temp + ((rowbase + r0 + 8) << 8) + col),
                       make_int2(cc[2], cc[3]));
            }

        // all ldsm reads of cbuf done + all STS to nbuf visible before next iter
        __syncthreads();
    }

    #pragma unroll
    for (int o = 16; o; o >>= 1) lmax = max(lmax, __shfl_xor_sync(0xffffffffu, lmax, o));
    if (lid == 0) red[wid] = lmax;
    __syncthreads();
    if (tid == 0) {
        int m = red[0];
        #pragma unroll
        for (int w = 1; w < 8; w++) m = max(m, red[w]);
        g_partial[blockIdx.x] = m;     // unconditional overwrite: replay-deterministic
    }
}

// ---------------- Phase 1: reduce partials -> round-shift -> fp32 out ----------------
__global__ void __launch_bounds__(THREADS)
finalize_kernel(const int* __restrict__ exp_in, const int* __restrict__ weight_exp,
                float* __restrict__ out, int exp_mode, int np)
{
    __shared__ int red[8];
    __shared__ int s_shift;
    const int tid = threadIdx.x;
    const int wid = tid >> 5;
    const int lid = tid & 31;

    // global max from per-CTA partials (np <= 2048; ~2 loads/thread)
    int m = 0;
    for (int i = tid; i < np; i += THREADS) m = max(m, g_partial[i]);
    #pragma unroll
    for (int o = 16; o; o >>= 1) m = max(m, __shfl_xor_sync(0xffffffffu, m, o));
    if (lid == 0) red[wid] = m;
    __syncthreads();
    if (tid == 0) {
        int rr = red[0];
        #pragma unroll
        for (int w = 1; w < 8; w++) rr = max(rr, red[w]);
        int bw = (rr > 0) ? (32 - __clz(rr - 1)) : 0;   // == ceil(log2(r)), r>=1
        s_shift = bw - 7;
    }
    __syncthreads();
    const int sh = s_shift;
    const bool pos = sh > 0;
    const int shift = pos ? sh : 1;

    // elementwise: read s32 temp, round-shift, write fp32 (memory-bound)
    const long long total4 = (long long)BATCH * NDIM / 4;
    const long long stride = (long long)gridDim.x * THREADS;
    for (long long i = (long long)blockIdx.x * THREADS + tid; i < total4; i += stride) {
        int4 t = __ldcs(reinterpret_cast<const int4*>(g_temp) + i);
        float4 o;
        o.x = round_shift_f(t.x, shift, pos);
        o.y = round_shift_f(t.y, shift, pos);
        o.z = round_shift_f(t.z, shift, pos);
        o.w = round_shift_f(t.w, shift, pos);
        __stcs(reinterpret_cast<float4*>(out) + i, o);
    }

    if (exp_mode != 0 && blockIdx.x == 0 && tid == 0) {
        int e = exp_in[0] + weight_exp[0] + (pos ? shift : 0);
        out[(size_t)BATCH * NDIM] = (float)e;   // exp_out as the trailing element
    }
}

extern "C" void kernel_launch(void* const* d_in, const int* in_sizes, int n_in,
                              void* d_out, int out_size) {
    const float* act        = (const float*)d_in[0];
    const int*   exp_in     = (const int*)d_in[1];
    const float* weight     = (const float*)d_in[2];
    const int*   weight_exp = (const int*)d_in[3];
    float*       out        = (float*)d_out;

    int nsm = 148;
    cudaDeviceGetAttribute(&nsm, cudaDevAttrMultiProcessorCount, 0);
    if (nsm <= 0) nsm = 148;
    int grid = 2 * nsm;                  // 2 CTAs/SM for cross-CTA mem/MMA overlap
    if (grid > NTILES) grid = NTILES;

    cudaFuncSetAttribute(gemm_kernel, cudaFuncAttributeMaxDynamicSharedMemorySize, SMEM_TOTAL);

    const long long n = (long long)BATCH * NDIM;
    // out_size is an ELEMENT count of the output dtype (float32). n act_out
    // values, optionally followed by exp_out as one extra element.
    int exp_mode = ((long long)out_size > n) ? 1 : 0;

    gemm_kernel<<<grid, THREADS, SMEM_TOTAL>>>(act, weight);
    finalize_kernel<<<8 * nsm, THREADS>>>(exp_in, weight_exp, out, exp_mode, grid);
}

// round 16
// speedup vs baseline: 1.4635x; 1.4635x over previous
#include <cuda_runtime.h>
#include <stdint.h>

#define DEVINL __device__ __forceinline__

static constexpr int BATCH  = 131072;
static constexpr int KDIM   = 256;
static constexpr int NDIM   = 256;
static constexpr int MTILE  = 64;
static constexpr int NTILES = BATCH / MTILE;   // 2048
static constexpr int THREADS = 256;            // 8 warps: 2x4 warp grid, warp tile 32x64
static constexpr int AFRAG  = MTILE * KDIM / 4;  // 4096 float4-equivalents per A tile

// Padded row stride (bytes) for s8 tiles in SMEM: 272 = 16*17.
// 272/4 = 68 == 4 (mod 32) -> 8 consecutive rows cover all 32 banks exactly
// once for 16B/row accesses: conflict-free ldmatrix and 16B vector copies.
static constexpr int ROWB = 272;
static constexpr int ATILE_B = MTILE * ROWB;    // 17408

static constexpr int SM_W  = 0;                 // W tile: 256 x 272 = 69632
static constexpr int SM_A0 = NDIM * ROWB;       // A ping  buffer
static constexpr int SM_A1 = SM_A0 + ATILE_B;   // A pong  buffer
static constexpr int SMEM_TOTAL = SM_A1 + ATILE_B;  // 104448 B -> 2 CTAs/SM

// per-CTA partial abs-max, fully overwritten by the GEMM kernel every replay
__device__ int g_partial[NTILES];
// raw s32 GEMM accumulators (gemm writes, finalize reads) — 128 MB static scratch
__device__ int g_temp[(size_t)BATCH * NDIM];

DEVINL uint32_t smem_u32(const void* p) {
    uint32_t a;
    asm("{ .reg .u64 t; cvta.to.shared.u64 t, %1; cvt.u32.u64 %0, t; }" : "=r"(a) : "l"(p));
    return a;
}

// ldmatrix x4 (b16 view of s8 data). sm_75+ PTX, no 'a'-target features.
DEVINL void ldsm4(uint32_t* r, uint32_t addr) {
    asm volatile("ldmatrix.sync.aligned.m8n8.x4.shared.b16 {%0,%1,%2,%3}, [%4];"
                 : "=r"(r[0]), "=r"(r[1]), "=r"(r[2]), "=r"(r[3]) : "r"(addr));
}

// s8 x s8 -> s32 mma (sm_80+): D[16x8] += A[16x32](row) * B[32x8](col)
DEVINL void mma_s8(int* c, const uint32_t* a, const uint32_t* b) {
    asm volatile(
        "mma.sync.aligned.m16n8k32.row.col.s32.s8.s8.s32 "
        "{%0,%1,%2,%3}, {%4,%5,%6,%7}, {%8,%9}, {%0,%1,%2,%3};"
        : "+r"(c[0]), "+r"(c[1]), "+r"(c[2]), "+r"(c[3])
        : "r"(a[0]), "r"(a[1]), "r"(a[2]), "r"(a[3]), "r"(b[0]), "r"(b[1]));
}

DEVINL uint32_t pack_s8(float4 f) {
    int b0 = __float2int_rn(f.x) & 255, b1 = __float2int_rn(f.y) & 255;
    int b2 = __float2int_rn(f.z) & 255, b3 = __float2int_rn(f.w) & 255;
    return (uint32_t)(b0 | (b1 << 8) | (b2 << 16) | (b3 << 24));
}

// RoundShift, exact integer replica of the fp reference. pos branch: floor-shift
// + remainder bit (s-1), clip [-127,127]. !pos branch: numpy astype(int8) wrap
// (exact: !pos implies |x| <= 128).
DEVINL float round_shift_f(int x, int shift, bool pos) {
    int v;
    if (pos) {
        v = (x >> shift) + ((x >> (shift - 1)) & 1);
        v = v < -127 ? -127 : (v > 127 ? 127 : v);
    } else {
        v = (int)(signed char)(x & 255);
    }
    return (float)v;
}

// store one packed A word into the padded s8 tile (f in [0, AFRAG))
DEVINL void sts_a(char* smem, int buf_off, int f, uint32_t u) {
    int row = f >> 6, fi = f & 63;
    *reinterpret_cast<uint32_t*>(smem + buf_off + row * ROWB + fi * 4) = u;
}

// ---------------- Phase 0: s8 GEMM -> raw s32 temp + per-CTA abs-max ----------------
__global__ void __launch_bounds__(THREADS, 2)
gemm_kernel(const float* __restrict__ act, const float* __restrict__ weight)
{
    extern __shared__ char smem[];
    __shared__ int red[8];
    const uint32_t sb = smem_u32(smem);
    const int tid = threadIdx.x;
    const int wid = tid >> 5;
    const int lid = tid & 31;
    const int mw = (wid >> 2) * 32;   // warp M base within the 64-row tile
    const int nw = (wid & 3) * 64;    // warp N base within 256 cols

    // stage W [N=256][K=256] fp32 -> s8, padded rows, once per CTA
    {
        const float4* w4 = reinterpret_cast<const float4*>(weight);
        for (int f = tid; f < NDIM * KDIM / 4; f += THREADS) {
            int row = f >> 6, fi = f & 63;              // 64 float4 per K-row
            *reinterpret_cast<uint32_t*>(smem + SM_W + row * ROWB + fi * 4) = pack_s8(w4[f]);
        }
    }

    int lmax = 0;
    const int gsz = (int)gridDim.x;
    const int c = (NTILES - (int)blockIdx.x + gsz - 1) / gsz;

    // prologue: plain-stage tile 0 into buffer 0
    {
        const float4* a4 = reinterpret_cast<const float4*>(act) + (size_t)blockIdx.x * AFRAG;
        #pragma unroll
        for (int i = 0; i < AFRAG / THREADS; i++) {
            int f = tid + i * THREADS;
            sts_a(smem, SM_A0, f, pack_s8(__ldcs(&a4[f])));
        }
    }
    __syncthreads();

    for (int j = 0; j < c; j++) {
        const int tile = (int)blockIdx.x + j * gsz;
        const int cbuf = SM_A0 + (j & 1) * ATILE_B;          // MMA reads this
        const int nbuf = SM_A0 + ((j + 1) & 1) * ATILE_B;    // prefetch writes this
        const bool pf = (j + 1 < c);
        const float4* a4n = reinterpret_cast<const float4*>(act)
                          + (size_t)(tile + gsz) * AFRAG;

        int acc[16][4];
        #pragma unroll
        for (int i = 0; i < 16; i++)
            #pragma unroll
            for (int r = 0; r < 4; r++) acc[i][r] = 0;

        // software pipeline: cur holds data for pack/STS this step; nxt in flight
        float4 cur0, cur1, nxt0, nxt1;
        if (pf) {
            cur0 = __ldcs(&a4n[tid]);
            cur1 = __ldcs(&a4n[tid + THREADS]);
        }

        // K=256 in 8 steps of 32, next-tile staging interleaved.
        // unroll 1 is load-bearing: full unroll blows the 128-reg cap (R13 regression).
        #pragma unroll 1
        for (int ks = 0; ks < 8; ks++) {
            // issue next prefetch loads early (latency hidden by ldsm+mma below)
            if (pf && ks < 7) {
                nxt0 = __ldcs(&a4n[tid + (2 * ks + 2) * THREADS]);
                nxt1 = __ldcs(&a4n[tid + (2 * ks + 3) * THREADS]);
            }

            const int kb = ks * 32;
            uint32_t a[2][4], b[8][2];
            #pragma unroll
            for (int mt = 0; mt < 2; mt++) {
                int row = mw + mt * 16 + ((lid >> 3) & 1) * 8 + (lid & 7);
                uint32_t addr = sb + cbuf + row * ROWB + kb + (((lid >> 4) & 1) << 4);
                ldsm4(a[mt], addr);
            }
            #pragma unroll
            for (int p = 0; p < 4; p++) {
                int nrow = nw + p * 16 + (((lid >> 4) & 1) << 3) + (lid & 7);
                uint32_t addr = sb + SM_W + nrow * ROWB + kb + (((lid >> 3) & 1) << 4);
                uint32_t t4[4];
                ldsm4(t4, addr);
                b[2 * p][0] = t4[0]; b[2 * p][1] = t4[1];
                b[2 * p + 1][0] = t4[2]; b[2 * p + 1][1] = t4[3];
            }
            #pragma unroll
            for (int mt = 0; mt < 2; mt++)
                #pragma unroll
                for (int nt = 0; nt < 8; nt++)
                    mma_s8(acc[mt * 8 + nt], a[mt], b[nt]);

            // pack + STS the pair loaded one step ago (into the inactive buffer)
            if (pf) {
                sts_a(smem, nbuf, tid + (2 * ks) * THREADS,     pack_s8(cur0));
                sts_a(smem, nbuf, tid + (2 * ks + 1) * THREADS, pack_s8(cur1));
                cur0 = nxt0;
                cur1 = nxt1;
            }
        }

        // epilogue: abs-max + raw s32 store (C quads -> 8B-aligned int2 stores)
        const size_t rowbase = (size_t)tile * MTILE;
        #pragma unroll
        for (int mt = 0; mt < 2; mt++)
            #pragma unroll
            for (int nt = 0; nt < 8; nt++) {
                const int* cc = acc[mt * 8 + nt];
                #pragma unroll
                for (int r = 0; r < 4; r++) {
                    int x = cc[r];
                    lmax = max(lmax, max(x, -x));
                }
                int r0  = mw + mt * 16 + (lid >> 2);
                int col = nw + nt * 8 + 2 * (lid & 3);
                __stcs(reinterpret_cast<int2*>(g_temp + ((rowbase + r0) << 8) + col),
                       make_int2(cc[0], cc[1]));
                __stcs(reinterpret_cast<int2*>(g_temp + ((rowbase + r0 + 8) << 8) + col),
                       make_int2(cc[2], cc[3]));
            }

        // all ldsm reads of cbuf done + all STS to nbuf visible before next iter
        __syncthreads();
    }

    #pragma unroll
    for (int o = 16; o; o >>= 1) lmax = max(lmax, __shfl_xor_sync(0xffffffffu, lmax, o));
    if (lid == 0) red[wid] = lmax;
    __syncthreads();
    if (tid == 0) {
        int m = red[0];
        #pragma unroll
        for (int w = 1; w < 8; w++) m = max(m, red[w]);
        g_partial[blockIdx.x] = m;     // unconditional overwrite: replay-deterministic
    }
}

// ---------------- Phase 1: reduce partials -> round-shift -> fp32 out ----------------
__global__ void __launch_bounds__(THREADS)
finalize_kernel(const int* __restrict__ exp_in, const int* __restrict__ weight_exp,
                float* __restrict__ out, int exp_mode, int np)
{
    __shared__ int red[8];
    __shared__ int s_shift;
    const int tid = threadIdx.x;
    const int wid = tid >> 5;
    const int lid = tid & 31;

    // global max from per-CTA partials (np <= 2048; ~2 loads/thread)
    int m = 0;
    for (int i = tid; i < np; i += THREADS) m = max(m, g_partial[i]);
    #pragma unroll
    for (int o = 16; o; o >>= 1) m = max(m, __shfl_xor_sync(0xffffffffu, m, o));
    if (lid == 0) red[wid] = m;
    __syncthreads();
    if (tid == 0) {
        int rr = red[0];
        #pragma unroll
        for (int w = 1; w < 8; w++) rr = max(rr, red[w]);
        int bw = (rr > 0) ? (32 - __clz(rr - 1)) : 0;   // == ceil(log2(r)), r>=1
        s_shift = bw - 7;
    }
    __syncthreads();
    const int sh = s_shift;
    const bool pos = sh > 0;
    const int shift = pos ? sh : 1;

    // elementwise: read s32 temp, round-shift, write fp32 (memory-bound)
    const long long total4 = (long long)BATCH * NDIM / 4;
    const long long stride = (long long)gridDim.x * THREADS;
    for (long long i = (long long)blockIdx.x * THREADS + tid; i < total4; i += stride) {
        int4 t = __ldcs(reinterpret_cast<const int4*>(g_temp) + i);
        float4 o;
        o.x = round_shift_f(t.x, shift, pos);
        o.y = round_shift_f(t.y, shift, pos);
        o.z = round_shift_f(t.z, shift, pos);
        o.w = round_shift_f(t.w, shift, pos);
        __stcs(reinterpret_cast<float4*>(out) + i, o);
    }

    if (exp_mode != 0 && blockIdx.x == 0 && tid == 0) {
        int e = exp_in[0] + weight_exp[0] + (pos ? shift : 0);
        out[(size_t)BATCH * NDIM] = (float)e;   // exp_out as the trailing element
    }
}

extern "C" void kernel_launch(void* const* d_in, const int* in_sizes, int n_in,
                              void* d_out, int out_size) {
    const float* act        = (const float*)d_in[0];
    const int*   exp_in     = (const int*)d_in[1];
    const float* weight     = (const float*)d_in[2];
    const int*   weight_exp = (const int*)d_in[3];
    float*       out        = (float*)d_out;

    int nsm = 148;
    cudaDeviceGetAttribute(&nsm, cudaDevAttrMultiProcessorCount, 0);
    if (nsm <= 0) nsm = 148;
    int grid = 2 * nsm;                  // 2 CTAs/SM for cross-CTA mem/MMA overlap
    if (grid > NTILES) grid = NTILES;

    cudaFuncSetAttribute(gemm_kernel, cudaFuncAttributeMaxDynamicSharedMemorySize, SMEM_TOTAL);

    const long long n = (long long)BATCH * NDIM;
    // out_size is an ELEMENT count of the output dtype (float32). n act_out
    // values, optionally followed by exp_out as one extra element.
    int exp_mode = ((long long)out_size > n) ? 1 : 0;

    gemm_kernel<<<grid, THREADS, SMEM_TOTAL>>>(act, weight);
    finalize_kernel<<<8 * nsm, THREADS>>>(exp_in, weight_exp, out, exp_mode, grid);
}